// round 2
// baseline (speedup 1.0000x reference)
#include <cuda_runtime.h>

#define N_NODES 20000
#define N_EDGES 320000
#define BATCH   4
#define F_IN    16
#define H_DIM   64
#define P_DIM   12
#define ROW     (F_IN * P_DIM)   // 192 floats per (b,n)

// ---------------- scratch (no allocations allowed) ----------------
__device__ float  g_deg[N_NODES];
__device__ float  g_dinv[N_NODES];
__device__ int    g_count[N_NODES];
__device__ int    g_offset[N_NODES];
__device__ int    g_cursor[N_NODES];
__device__ float2 g_csr[N_EDGES];          // {src as int bits, norm}
__device__ float  g_Mz[F_IN * H_DIM];
__device__ float  g_Mh[F_IN * H_DIM];
__device__ float  g_bZ[H_DIM];
__device__ float  g_bH[H_DIM];
__device__ float  g_probs[P_DIM];
__device__ int    g_is64;

// ---------------- dtype detection (int64 vs silently-downcast int32) -------
__global__ void k_detect(const void* __restrict__ ei) {
    const unsigned long long* p = (const unsigned long long*)ei;
    int is64 = 1;
    #pragma unroll 1
    for (int i = 0; i < 64; i++)
        if (p[i] > (unsigned long long)N_NODES) { is64 = 0; break; }
    g_is64 = is64;
}

__device__ __forceinline__ int load_idx(const void* __restrict__ ei,
                                        int which, int e, int is64) {
    if (is64) return (int)((const long long*)ei)[(size_t)which * N_EDGES + e];
    return ((const int*)ei)[(size_t)which * N_EDGES + e];
}

// ---------------- small kernels ----------------
__global__ void k_init() {
    int i = blockIdx.x * blockDim.x + threadIdx.x;
    if (i < N_NODES) { g_deg[i] = 1.0f; g_count[i] = 0; }  // deg starts at self-loop weight
}

// Fuse GCN weight with linear-top weight: Mz = Wg_z @ Wl_z[:H], biases fold too.
__global__ void k_setup(const float* __restrict__ Wg_z, const float* __restrict__ bg_z,
                        const float* __restrict__ Wg_h, const float* __restrict__ bg_h,
                        const float* __restrict__ Wl_z, const float* __restrict__ bl_z,
                        const float* __restrict__ Wl_h, const float* __restrict__ bl_h,
                        const float* __restrict__ att) {
    int t = threadIdx.x;          // 1024 threads
    int f = t >> 6, h = t & 63;
    float sz = 0.f, sh = 0.f;
    #pragma unroll 8
    for (int j = 0; j < H_DIM; j++) {
        sz += Wg_z[f * H_DIM + j] * Wl_z[j * H_DIM + h];
        sh += Wg_h[f * H_DIM + j] * Wl_h[j * H_DIM + h];
    }
    g_Mz[t] = sz; g_Mh[t] = sh;
    if (t < H_DIM) {
        float bz = bl_z[t], bh = bl_h[t];
        for (int j = 0; j < H_DIM; j++) {
            bz += bg_z[j] * Wl_z[j * H_DIM + t];
            bh += bg_h[j] * Wl_h[j * H_DIM + t];
        }
        g_bZ[t] = bz; g_bH[t] = bh;
    }
    if (t == 0) {
        float m = att[0];
        for (int p = 1; p < P_DIM; p++) m = fmaxf(m, att[p]);
        float e[P_DIM], s = 0.f;
        for (int p = 0; p < P_DIM; p++) { e[p] = expf(att[p] - m); s += e[p]; }
        float inv = 1.f / s;
        for (int p = 0; p < P_DIM; p++) g_probs[p] = e[p] * inv;
    }
}

__global__ void k_degree(const void* __restrict__ ei, const float* __restrict__ ew) {
    int e = blockIdx.x * blockDim.x + threadIdx.x;
    int is64 = g_is64;
    if (e < N_EDGES) {
        int d = load_idx(ei, 1, e, is64);
        atomicAdd(&g_deg[d], ew[e]);
        atomicAdd(&g_count[d], 1);
    }
}

// Exclusive scan of counts (single block), plus dinv + cursor init.
__global__ void k_scan() {
    __shared__ int sdata[1024];
    __shared__ int running;
    int tid = threadIdx.x;
    if (tid == 0) running = 0;
    __syncthreads();
    for (int base = 0; base < N_NODES; base += 1024) {
        int i = base + tid;
        int v = (i < N_NODES) ? g_count[i] : 0;
        sdata[tid] = v;
        __syncthreads();
        for (int off = 1; off < 1024; off <<= 1) {
            int t = (tid >= off) ? sdata[tid - off] : 0;
            __syncthreads();
            sdata[tid] += t;
            __syncthreads();
        }
        int excl = sdata[tid] - v + running;
        if (i < N_NODES) {
            g_offset[i] = excl;
            g_cursor[i] = excl;
            g_dinv[i]   = rsqrtf(g_deg[i]);   // deg >= 1 always (self loop)
        }
        __syncthreads();
        if (tid == 0) running += sdata[1023];
        __syncthreads();
    }
}

__global__ void k_fill(const void* __restrict__ ei, const float* __restrict__ ew) {
    int e = blockIdx.x * blockDim.x + threadIdx.x;
    int is64 = g_is64;
    if (e < N_EDGES) {
        int s = load_idx(ei, 0, e, is64);
        int d = load_idx(ei, 1, e, is64);
        float norm = g_dinv[s] * ew[e] * g_dinv[d];
        int pos = atomicAdd(&g_cursor[d], 1);
        g_csr[pos] = make_float2(__int_as_float(s), norm);
    }
}

__device__ __forceinline__ float tanh_fast(float x) {
    // tanh(x) = 1 - 2/(exp(2x)+1); saturates correctly at +/-inf of __expf
    float e = __expf(2.f * x);
    return 1.f - 2.f / (e + 1.f);
}

// ---------------- fused gather + GRU + attention + output ----------------
// One warp per (b, n). agg held in registers during gather, staged in smem for
// the p-loop (broadcast reads). Composite weights live in registers per lane
// (lane l owns output channels h = l and h = l+32), amortized over a task loop.
__launch_bounds__(256, 2)
__global__ void k_main(const float* __restrict__ x,
                       const float* __restrict__ W_out,
                       const float* __restrict__ b_out,
                       float* __restrict__ out) {
    __shared__ float sAgg[8][ROW];
    __shared__ float sH[8][H_DIM];
    __shared__ float sW[H_DIM * P_DIM];
    __shared__ float sB[P_DIM];
    __shared__ float sP[P_DIM];

    int tid = threadIdx.x;
    for (int i = tid; i < H_DIM * P_DIM; i += 256) sW[i] = W_out[i];
    if (tid < P_DIM) { sB[tid] = b_out[tid]; sP[tid] = g_probs[tid]; }

    int l = tid & 31, w = tid >> 5;

    float wz0[F_IN], wz1[F_IN], wh0[F_IN], wh1[F_IN];
    #pragma unroll
    for (int f = 0; f < F_IN; f++) {
        wz0[f] = g_Mz[f * H_DIM + l];
        wz1[f] = g_Mz[f * H_DIM + l + 32];
        wh0[f] = g_Mh[f * H_DIM + l];
        wh1[f] = g_Mh[f * H_DIM + l + 32];
    }
    float bz0 = g_bZ[l], bz1 = g_bZ[l + 32];
    float bh0 = g_bH[l], bh1 = g_bH[l + 32];
    __syncthreads();

    int gw = blockIdx.x * 8 + w;
    int nwarps = gridDim.x * 8;

    for (int task = gw; task < BATCH * N_NODES; task += nwarps) {
        int b = task & 3;
        int n = task >> 2;

        // ---- gather (CSR over incoming edges + self loop) ----
        float dn = g_dinv[n];
        float swgt = dn * dn;                      // self-loop norm
        const float2* xr = (const float2*)(x + ((size_t)b * N_NODES + n) * ROW);
        float2 v;
        float a0x, a0y, a1x, a1y, a2x, a2y;
        v = __ldg(&xr[l]);      a0x = swgt * v.x; a0y = swgt * v.y;
        v = __ldg(&xr[32 + l]); a1x = swgt * v.x; a1y = swgt * v.y;
        v = __ldg(&xr[64 + l]); a2x = swgt * v.x; a2y = swgt * v.y;

        int beg = g_offset[n];
        int cnt = g_count[n];
        for (int j = 0; j < cnt; j++) {
            float2 cw = g_csr[beg + j];
            int   s  = __float_as_int(cw.x);
            float wt = cw.y;
            const float2* xs = (const float2*)(x + ((size_t)b * N_NODES + s) * ROW);
            v = __ldg(&xs[l]);      a0x += wt * v.x; a0y += wt * v.y;
            v = __ldg(&xs[32 + l]); a1x += wt * v.x; a1y += wt * v.y;
            v = __ldg(&xs[64 + l]); a2x += wt * v.x; a2y += wt * v.y;
        }
        float2* sA2 = (float2*)sAgg[w];
        sA2[l]      = make_float2(a0x, a0y);
        sA2[32 + l] = make_float2(a1x, a1y);
        sA2[64 + l] = make_float2(a2x, a2y);
        __syncwarp();

        // ---- per-period collapsed GRU + attention pooling ----
        float hacc0 = 0.f, hacc1 = 0.f;
        #pragma unroll 3
        for (int p = 0; p < P_DIM; p++) {
            float uz0 = bz0, uz1 = bz1, uh0 = bh0, uh1 = bh1;
            #pragma unroll
            for (int f = 0; f < F_IN; f++) {
                float a = sAgg[w][f * P_DIM + p];   // uniform -> smem broadcast
                uz0 += a * wz0[f];
                uz1 += a * wz1[f];
                uh0 += a * wh0[f];
                uh1 += a * wh1[f];
            }
            // (1 - sigmoid(u)) = 1/(1+exp(u))
            float z0 = 1.f / (1.f + __expf(uz0));
            float z1 = 1.f / (1.f + __expf(uz1));
            float t0 = tanh_fast(uh0);
            float t1 = tanh_fast(uh1);
            float pr = sP[p];
            hacc0 += pr * z0 * t0;
            hacc1 += pr * z1 * t1;
        }
        sH[w][l]      = fmaxf(hacc0, 0.f);
        sH[w][l + 32] = fmaxf(hacc1, 0.f);
        __syncwarp();

        // ---- trailing linear: out[b,n,q] = relu(Hacc) . W_out[:,q] + b_out[q]
        if (l < P_DIM) {
            float o = sB[l];
            #pragma unroll
            for (int h = 0; h < H_DIM; h++)
                o += sH[w][h] * sW[h * P_DIM + l];
            out[((size_t)b * N_NODES + n) * P_DIM + l] = o;
        }
        __syncwarp();   // protect sAgg/sH before next task overwrites
    }
}

// ---------------- launch ----------------
extern "C" void kernel_launch(void* const* d_in, const int* in_sizes, int n_in,
                              void* d_out, int out_size) {
    const float* x     = (const float*)d_in[0];
    const void*  ei    = d_in[1];              // int64 or (silently) int32 — detected on device
    const float* ew    = (const float*)d_in[2];
    const float* Wg_z  = (const float*)d_in[3];
    const float* bg_z  = (const float*)d_in[4];
    // d_in[5], d_in[6]: Wg_r/bg_r  — dead (multiplied into H0*R = 0)
    const float* Wg_h  = (const float*)d_in[7];
    const float* bg_h  = (const float*)d_in[8];
    const float* Wl_z  = (const float*)d_in[9];
    const float* bl_z  = (const float*)d_in[10];
    // d_in[11], d_in[12]: Wl_r/bl_r — dead
    const float* Wl_h  = (const float*)d_in[13];
    const float* bl_h  = (const float*)d_in[14];
    const float* att   = (const float*)d_in[15];
    const float* W_out = (const float*)d_in[16];
    const float* b_out = (const float*)d_in[17];
    float*       out   = (float*)d_out;

    k_detect<<<1, 1>>>(ei);
    k_init  <<<(N_NODES + 255) / 256, 256>>>();
    k_setup <<<1, 1024>>>(Wg_z, bg_z, Wg_h, bg_h, Wl_z, bl_z, Wl_h, bl_h, att);
    k_degree<<<(N_EDGES + 255) / 256, 256>>>(ei, ew);
    k_scan  <<<1, 1024>>>();
    k_fill  <<<(N_EDGES + 255) / 256, 256>>>(ei, ew);
    k_main  <<<1000, 256>>>(x, W_out, b_out, out);
}